// round 6
// baseline (speedup 1.0000x reference)
#include <cuda_runtime.h>
#include <cstdint>

#define B_      32
#define N_      500
#define D_      2048
#define K_      128
#define SIGMA   0.05f
#define THREADS 256          // 8 contiguous elements per thread

__device__ float g_xk[B_];   // safe lower bound of K-th largest of x per row

// monotone float -> uint (bigger float -> bigger uint)
__device__ __forceinline__ unsigned int f2u(float f) {
    unsigned int u = __float_as_uint(f);
    return u ^ (((unsigned int)((int)u >> 31)) | 0x80000000u);
}
__device__ __forceinline__ float u2f(unsigned int u) {
    unsigned int v = (u & 0x80000000u) ? (u ^ 0x80000000u) : ~u;
    return __uint_as_float(v);
}

// exclusive block scan over 256 threads (8 warps); returns total. 16+16 packed safe.
__device__ __forceinline__ unsigned int block_scan_excl(unsigned int v,
                                                        unsigned int* warpSums,
                                                        unsigned int* total) {
    const int lane = threadIdx.x & 31;
    const int wid  = threadIdx.x >> 5;
    unsigned int x = v;
    #pragma unroll
    for (int o = 1; o < 32; o <<= 1) {
        unsigned int y = __shfl_up_sync(0xffffffffu, x, o);
        if (lane >= o) x += y;
    }
    if (lane == 31) warpSums[wid] = x;
    __syncthreads();
    if (wid == 0 && lane < 8) {
        unsigned int s = warpSums[lane];
        #pragma unroll
        for (int o = 1; o < 8; o <<= 1) {
            unsigned int y = __shfl_up_sync(0xffu, s, o);
            if (lane >= o) s += y;
        }
        warpSums[lane] = s;
    }
    __syncthreads();
    unsigned int base = (wid > 0) ? warpSums[wid - 1] : 0u;
    unsigned int tot  = warpSums[7];
    __syncthreads();
    *total = tot;
    return base + x - v;
}

// ---- prep kernel: blocks 0..31 compute xK(row); blocks 32.. zero `ind` ----
#define PREP_BLOCKS 2048
__global__ __launch_bounds__(THREADS)
void prep_kernel(const float* __restrict__ x, float4* __restrict__ ind4, int n4) {
    __shared__ unsigned int hist[256];
    __shared__ unsigned int sh_sel, sh_krem, sh_done;

    const int t = threadIdx.x;

    if (blockIdx.x >= B_) {
        if (ind4) {
            float4 z = make_float4(0.f, 0.f, 0.f, 0.f);
            int stride = (PREP_BLOCKS - B_) * THREADS;
            for (int i = (blockIdx.x - B_) * THREADS + t; i < n4; i += stride)
                ind4[i] = z;
        }
        return;
    }

    const int lane = t & 31, wid = t >> 5;
    const int b = blockIdx.x;

    unsigned int k[8];
    {
        const float4* xv = (const float4*)(x + (size_t)b * D_);
        float4 a = xv[2 * t], c = xv[2 * t + 1];
        k[0] = f2u(a.x); k[1] = f2u(a.y); k[2] = f2u(a.z); k[3] = f2u(a.w);
        k[4] = f2u(c.x); k[5] = f2u(c.y); k[6] = f2u(c.z); k[7] = f2u(c.w);
    }

    unsigned int pref = 0, maskH = 0, krem = K_, done = 0;
    for (int pass = 0; pass < 4; pass++) {
        const int shift = 24 - pass * 8;
        hist[t] = 0u;
        __syncthreads();
        #pragma unroll
        for (int i = 0; i < 8; i++) {
            unsigned int kk = k[i];
            if ((kk & maskH) == pref)
                atomicAdd(&hist[(kk >> shift) & 0xFFu], 1u);
        }
        __syncthreads();
        if (wid == 0) {
            unsigned int c[8], s = 0;
            #pragma unroll
            for (int i = 0; i < 8; i++) { c[i] = hist[lane * 8 + i]; s += c[i]; }
            unsigned int xs = s;
            #pragma unroll
            for (int o = 1; o < 32; o <<= 1) {
                unsigned int y = __shfl_up_sync(0xffffffffu, xs, o);
                if (lane >= o) xs += y;
            }
            unsigned int tot = __shfl_sync(0xffffffffu, xs, 31);
            unsigned int run = xs - s;
            #pragma unroll
            for (int i = 0; i < 8; i++) {
                unsigned int sfx = tot - run, after = sfx - c[i];
                if (sfx >= krem && after < krem) {
                    sh_sel = (unsigned int)(lane * 8 + i);
                    sh_krem = krem - after;
                    sh_done = (sfx == krem);
                }
                run += c[i];
            }
        }
        __syncthreads();
        pref |= (sh_sel << shift); maskH |= (0xFFu << shift);
        krem = sh_krem; done = sh_done;
        if (done) break;
    }
    if (t == 0) g_xk[b] = u2f(pref);
}

// ---- main kernel ----
__global__ __launch_bounds__(THREADS)
void perturbed_topk_kernel(const float* __restrict__ x,
                           const float* __restrict__ noise,
                           float* __restrict__ ind,    // (B,K,D) or null
                           float* __restrict__ idxf)   // (B,N,K) or null
{
    __shared__ unsigned int  ckey[D_];
    __shared__ unsigned short cidx[D_];
    __shared__ unsigned int  hist[256];
    __shared__ unsigned int  warpSums[8];
    __shared__ float         warpMax[8];
    __shared__ unsigned int  warpAnd[8], warpOr[8];
    __shared__ float         sh_L;
    __shared__ unsigned int  sh_sel, sh_krem, sh_done;
    __shared__ unsigned int  sh_pref, sh_mask;
    __shared__ int           sh_pass0;

    const int t = threadIdx.x, lane = t & 31, wid = t >> 5;
    const int b = blockIdx.x / N_;

    // load + perturb (thread t owns elems 8t..8t+7), track row max |noise|
    float kf[8];
    float am = 0.f;
    {
        const float4* xv = (const float4*)(x + (size_t)b * D_);
        const float4* nv = (const float4*)(noise + (size_t)blockIdx.x * D_);
        float4 X0 = xv[2 * t], X1 = xv[2 * t + 1];
        float4 N0 = nv[2 * t], N1 = nv[2 * t + 1];
        kf[0] = fmaf(SIGMA, N0.x, X0.x); am = fmaxf(am, fabsf(N0.x));
        kf[1] = fmaf(SIGMA, N0.y, X0.y); am = fmaxf(am, fabsf(N0.y));
        kf[2] = fmaf(SIGMA, N0.z, X0.z); am = fmaxf(am, fabsf(N0.z));
        kf[3] = fmaf(SIGMA, N0.w, X0.w); am = fmaxf(am, fabsf(N0.w));
        kf[4] = fmaf(SIGMA, N1.x, X1.x); am = fmaxf(am, fabsf(N1.x));
        kf[5] = fmaf(SIGMA, N1.y, X1.y); am = fmaxf(am, fabsf(N1.y));
        kf[6] = fmaf(SIGMA, N1.z, X1.z); am = fmaxf(am, fabsf(N1.z));
        kf[7] = fmaf(SIGMA, N1.w, X1.w); am = fmaxf(am, fabsf(N1.w));
    }
    #pragma unroll
    for (int o = 16; o > 0; o >>= 1)
        am = fmaxf(am, __shfl_xor_sync(0xffffffffu, am, o));
    if (lane == 0) warpMax[wid] = am;
    __syncthreads();
    if (t == 0) {
        float m = warpMax[0];
        #pragma unroll
        for (int w = 1; w < 8; w++) m = fmaxf(m, warpMax[w]);
        // safe lower bound on the K-th largest perturbed key
        sh_L = g_xk[b] - SIGMA * m - 1e-4f;
    }
    __syncthreads();
    const unsigned int Lu = f2u(sh_L);

    // candidate mask + AND/OR over candidate keys (for common-prefix skip)
    unsigned int ku[8], m8 = 0;
    unsigned int av = 0xFFFFFFFFu, ov = 0u;
    #pragma unroll
    for (int i = 0; i < 8; i++) {
        ku[i] = f2u(kf[i]);
        bool c = (ku[i] >= Lu);
        m8 |= c ? (1u << i) : 0u;
        av &= c ? ku[i] : 0xFFFFFFFFu;
        ov |= c ? ku[i] : 0u;
    }
    #pragma unroll
    for (int o = 16; o > 0; o >>= 1) {
        av &= __shfl_xor_sync(0xffffffffu, av, o);
        ov |= __shfl_xor_sync(0xffffffffu, ov, o);
    }
    if (lane == 0) { warpAnd[wid] = av; warpOr[wid] = ov; }

    // compaction positions (block scan has its own barriers protecting warpAnd/Or)
    unsigned int tot;
    unsigned int pos = block_scan_excl(__popc(m8), warpSums, &tot);
    const int cnt = (int)tot;          // >= K guaranteed, <= 2048

    if (t == 0) {
        unsigned int A = warpAnd[0], O = warpOr[0];
        #pragma unroll
        for (int w = 1; w < 8; w++) { A &= warpAnd[w]; O |= warpOr[w]; }
        unsigned int xo = A ^ O;
        if (xo == 0u) {                 // all candidate keys identical
            sh_pass0 = 4;               // skip radix entirely
            sh_pref  = A;
            sh_mask  = 0xFFFFFFFFu;
            sh_krem  = K_;
            sh_done  = 1u;
        } else {
            int topByte = (31 - __clz(xo)) >> 3;     // 3 = MSB
            int p0 = 3 - topByte;                    // first pass that can differ
            unsigned int mH = (p0 > 0) ? (0xFFFFFFFFu << (32 - 8 * p0)) : 0u;
            sh_pass0 = p0;
            sh_pref  = A & mH;
            sh_mask  = mH;
        }
    }
    unsigned int mm = m8;
    while (mm) {
        int i = __ffs(mm) - 1;
        mm &= mm - 1;
        ckey[pos] = ku[i];
        cidx[pos] = (unsigned short)(8 * t + i);
        pos++;
    }
    __syncthreads();

    // radix select over the cnt candidates, starting at first differing byte
    const int pass0 = sh_pass0;
    unsigned int pref = sh_pref, maskH = sh_mask;
    unsigned int krem = (pass0 >= 4) ? sh_krem : K_;
    unsigned int done = (pass0 >= 4) ? sh_done : 0u;

    for (int pass = pass0; pass < 4; pass++) {
        const int shift = 24 - pass * 8;
        hist[t] = 0u;
        __syncthreads();
        for (int i = t; i < cnt; i += THREADS) {
            unsigned int u = ckey[i];
            if ((u & maskH) == pref)
                atomicAdd(&hist[(u >> shift) & 0xFFu], 1u);
        }
        __syncthreads();
        if (wid == 0) {
            unsigned int c[8], s = 0;
            #pragma unroll
            for (int i = 0; i < 8; i++) { c[i] = hist[lane * 8 + i]; s += c[i]; }
            unsigned int xs = s;
            #pragma unroll
            for (int o = 1; o < 32; o <<= 1) {
                unsigned int y = __shfl_up_sync(0xffffffffu, xs, o);
                if (lane >= o) xs += y;
            }
            unsigned int tt = __shfl_sync(0xffffffffu, xs, 31);
            unsigned int run = xs - s;
            #pragma unroll
            for (int i = 0; i < 8; i++) {
                unsigned int sfx = tt - run, after = sfx - c[i];
                if (sfx >= krem && after < krem) {
                    sh_sel = (unsigned int)(lane * 8 + i);
                    sh_krem = krem - after;
                    sh_done = (sfx == krem);
                }
                run += c[i];
            }
        }
        __syncthreads();
        pref |= (sh_sel << shift); maskH |= (0xFFu << shift);
        krem = sh_krem; done = sh_done;
        if (done) break;
    }
    const unsigned int T = pref;
    const unsigned int R = done ? (unsigned int)K_ : krem;

    // contiguous-chunk ownership keeps array (= index) order for the rank scan
    const int ept = (cnt + THREADS - 1) / THREADS;   // usually 1
    const int beg = t * ept;
    int end = beg + ept; if (end > cnt) end = cnt;

    unsigned int gt = 0, eq = 0;
    for (int i = beg; i < end; i++) {
        unsigned int u = ckey[i];
        gt += (u > T);
        eq += (u == T);
    }
    unsigned int tot2;
    unsigned int pr = block_scan_excl(gt | (eq << 16), warpSums, &tot2);
    unsigned int gtB = pr & 0xFFFFu;
    unsigned int eqB = pr >> 16;

    unsigned int j = gtB + ((eqB < R) ? eqB : R);
    unsigned int eqRank = eqB;
    const size_t idxBase = (size_t)blockIdx.x * K_;
    const float inv_n = 1.0f / (float)N_;

    for (int i = beg; i < end; i++) {
        unsigned int u = ckey[i];
        bool isEq = (u == T);
        bool sel  = (u > T) || (isEq && (eqRank < R));
        eqRank += isEq ? 1u : 0u;
        if (sel) {
            int e = (int)cidx[i];
            if (idxf) idxf[idxBase + j] = (float)e;
            if (ind)  atomicAdd(&ind[((size_t)b * K_ + j) * D_ + e], inv_n);
            j++;
        }
    }
}

extern "C" void kernel_launch(void* const* d_in, const int* in_sizes, int n_in,
                              void* d_out, int out_size) {
    const float* x     = (const float*)d_in[0];
    const float* noise = (const float*)d_in[1];
    if (n_in >= 2 && in_sizes[0] != B_ * D_) {
        x     = (const float*)d_in[1];
        noise = (const float*)d_in[0];
    }

    const long long IND = (long long)B_ * K_ * D_;   // 8388608
    const long long IDX = (long long)B_ * N_ * K_;   // 2048000

    float* ind  = nullptr;
    float* idxf = nullptr;
    if ((long long)out_size >= IND + IDX) {
        ind  = (float*)d_out;
        idxf = (float*)d_out + IND;
    } else if ((long long)out_size == IND) {
        ind = (float*)d_out;
    } else if ((long long)out_size == IDX) {
        idxf = (float*)d_out;
    } else {
        ind = (float*)d_out;
    }

    prep_kernel<<<PREP_BLOCKS, THREADS>>>(x, (float4*)ind, (int)(IND / 4));
    perturbed_topk_kernel<<<B_ * N_, THREADS>>>(x, noise, ind, idxf);
}

// round 7
// speedup vs baseline: 1.0668x; 1.0668x over previous
#include <cuda_runtime.h>
#include <cstdint>

#define B_      32
#define N_      500
#define D_      2048
#define K_      128
#define SIGMA   0.05f
#define THREADS 256          // 8 contiguous elements per thread

__device__ float g_xk[B_];   // safe lower bound of K-th largest of x per row

// monotone float -> uint (bigger float -> bigger uint)
__device__ __forceinline__ unsigned int f2u(float f) {
    unsigned int u = __float_as_uint(f);
    return u ^ (((unsigned int)((int)u >> 31)) | 0x80000000u);
}
__device__ __forceinline__ float u2f(unsigned int u) {
    unsigned int v = (u & 0x80000000u) ? (u ^ 0x80000000u) : ~u;
    return __uint_as_float(v);
}

// exclusive block scan over 256 threads (8 warps); returns total.
// Caller provides a dedicated warpSums buffer; NO trailing barrier —
// safe as long as that buffer isn't written again before the next barrier.
__device__ __forceinline__ unsigned int block_scan_excl(unsigned int v,
                                                        unsigned int* warpSums,
                                                        unsigned int* total) {
    const int lane = threadIdx.x & 31;
    const int wid  = threadIdx.x >> 5;
    unsigned int x = v;
    #pragma unroll
    for (int o = 1; o < 32; o <<= 1) {
        unsigned int y = __shfl_up_sync(0xffffffffu, x, o);
        if (lane >= o) x += y;
    }
    if (lane == 31) warpSums[wid] = x;
    __syncthreads();
    if (wid == 0 && lane < 8) {
        unsigned int s = warpSums[lane];
        #pragma unroll
        for (int o = 1; o < 8; o <<= 1) {
            unsigned int y = __shfl_up_sync(0xffu, s, o);
            if (lane >= o) s += y;
        }
        warpSums[lane] = s;
    }
    __syncthreads();
    unsigned int base = (wid > 0) ? warpSums[wid - 1] : 0u;
    *total = warpSums[7];
    return base + x - v;
}

// ---- prep kernel: blocks 0..31 compute xK(row); blocks 32.. zero `ind` ----
#define PREP_BLOCKS 2048
__global__ __launch_bounds__(THREADS)
void prep_kernel(const float* __restrict__ x, float4* __restrict__ ind4, int n4) {
    __shared__ unsigned int hist[256];
    __shared__ unsigned int sh_sel, sh_krem, sh_done;

    const int t = threadIdx.x;

    if (blockIdx.x >= B_) {
        if (ind4) {
            float4 z = make_float4(0.f, 0.f, 0.f, 0.f);
            int stride = (PREP_BLOCKS - B_) * THREADS;
            for (int i = (blockIdx.x - B_) * THREADS + t; i < n4; i += stride)
                ind4[i] = z;
        }
        return;
    }

    const int lane = t & 31, wid = t >> 5;
    const int b = blockIdx.x;

    unsigned int k[8];
    {
        const float4* xv = (const float4*)(x + (size_t)b * D_);
        float4 a = xv[2 * t], c = xv[2 * t + 1];
        k[0] = f2u(a.x); k[1] = f2u(a.y); k[2] = f2u(a.z); k[3] = f2u(a.w);
        k[4] = f2u(c.x); k[5] = f2u(c.y); k[6] = f2u(c.z); k[7] = f2u(c.w);
    }

    unsigned int pref = 0, maskH = 0, krem = K_, done = 0;
    for (int pass = 0; pass < 4; pass++) {
        const int shift = 24 - pass * 8;
        hist[t] = 0u;
        __syncthreads();
        #pragma unroll
        for (int i = 0; i < 8; i++) {
            unsigned int kk = k[i];
            if ((kk & maskH) == pref)
                atomicAdd(&hist[(kk >> shift) & 0xFFu], 1u);
        }
        __syncthreads();
        if (wid == 0) {
            unsigned int c[8], s = 0;
            #pragma unroll
            for (int i = 0; i < 8; i++) { c[i] = hist[lane * 8 + i]; s += c[i]; }
            unsigned int xs = s;
            #pragma unroll
            for (int o = 1; o < 32; o <<= 1) {
                unsigned int y = __shfl_up_sync(0xffffffffu, xs, o);
                if (lane >= o) xs += y;
            }
            unsigned int tot = __shfl_sync(0xffffffffu, xs, 31);
            unsigned int run = xs - s;
            #pragma unroll
            for (int i = 0; i < 8; i++) {
                unsigned int sfx = tot - run, after = sfx - c[i];
                if (sfx >= krem && after < krem) {
                    sh_sel = (unsigned int)(lane * 8 + i);
                    sh_krem = krem - after;
                    sh_done = (sfx == krem);
                }
                run += c[i];
            }
        }
        __syncthreads();
        pref |= (sh_sel << shift); maskH |= (0xFFu << shift);
        krem = sh_krem; done = sh_done;
        if (done) break;
    }
    if (t == 0) g_xk[b] = u2f(pref);
}

// ---- main kernel ----
__global__ __launch_bounds__(THREADS)
void perturbed_topk_kernel(const float* __restrict__ x,
                           const float* __restrict__ noise,
                           float* __restrict__ ind,    // (B,K,D) or null
                           float* __restrict__ idxf)   // (B,N,K) or null
{
    __shared__ unsigned int   ckey[D_];
    __shared__ unsigned short cidx[D_];
    __shared__ unsigned int   hist[256];
    __shared__ unsigned int   scanA[8], scanB[8];
    __shared__ float          warpMax[8];
    __shared__ float          sh_L;
    __shared__ unsigned int   sh_sel, sh_krem, sh_done;

    const int t = threadIdx.x, lane = t & 31, wid = t >> 5;
    const int b = blockIdx.x / N_;

    // load + perturb (thread t owns elems 8t..8t+7), track row max |noise|
    float kf[8];
    float am = 0.f;
    {
        const float4* xv = (const float4*)(x + (size_t)b * D_);
        const float4* nv = (const float4*)(noise + (size_t)blockIdx.x * D_);
        float4 X0 = xv[2 * t], X1 = xv[2 * t + 1];
        float4 N0 = nv[2 * t], N1 = nv[2 * t + 1];
        kf[0] = fmaf(SIGMA, N0.x, X0.x); am = fmaxf(am, fabsf(N0.x));
        kf[1] = fmaf(SIGMA, N0.y, X0.y); am = fmaxf(am, fabsf(N0.y));
        kf[2] = fmaf(SIGMA, N0.z, X0.z); am = fmaxf(am, fabsf(N0.z));
        kf[3] = fmaf(SIGMA, N0.w, X0.w); am = fmaxf(am, fabsf(N0.w));
        kf[4] = fmaf(SIGMA, N1.x, X1.x); am = fmaxf(am, fabsf(N1.x));
        kf[5] = fmaf(SIGMA, N1.y, X1.y); am = fmaxf(am, fabsf(N1.y));
        kf[6] = fmaf(SIGMA, N1.z, X1.z); am = fmaxf(am, fabsf(N1.z));
        kf[7] = fmaf(SIGMA, N1.w, X1.w); am = fmaxf(am, fabsf(N1.w));
    }
    #pragma unroll
    for (int o = 16; o > 0; o >>= 1)
        am = fmaxf(am, __shfl_xor_sync(0xffffffffu, am, o));
    if (lane == 0) warpMax[wid] = am;
    __syncthreads();
    if (t == 0) {
        float m = warpMax[0];
        #pragma unroll
        for (int w = 1; w < 8; w++) m = fmaxf(m, warpMax[w]);
        // safe lower bound on the K-th largest perturbed key
        sh_L = g_xk[b] - SIGMA * m - 1e-4f;
    }
    __syncthreads();
    const float L = sh_L;

    // candidate mask in FLOAT domain (f2u deferred to compaction)
    unsigned int m8 = 0;
    #pragma unroll
    for (int i = 0; i < 8; i++)
        m8 |= (kf[i] >= L) ? (1u << i) : 0u;

    unsigned int tot;
    unsigned int pos = block_scan_excl(__popc(m8), scanA, &tot);
    const int cnt = (int)tot;          // >= K guaranteed, <= 2048

    unsigned int mm = m8;
    while (mm) {
        int i = __ffs(mm) - 1;
        mm &= mm - 1;
        ckey[pos] = f2u(kf[i]);
        cidx[pos] = (unsigned short)(8 * t + i);
        pos++;
    }
    __syncthreads();

    // radix select over the cnt candidates (typically ~200 -> <=1 per thread)
    unsigned int pref = 0, maskH = 0, krem = K_, done = 0;
    for (int pass = 0; pass < 4; pass++) {
        const int shift = 24 - pass * 8;
        hist[t] = 0u;
        __syncthreads();
        for (int i = t; i < cnt; i += THREADS) {
            unsigned int u = ckey[i];
            if ((u & maskH) == pref)
                atomicAdd(&hist[(u >> shift) & 0xFFu], 1u);
        }
        __syncthreads();
        if (wid == 0) {
            unsigned int c[8], s = 0;
            #pragma unroll
            for (int i = 0; i < 8; i++) { c[i] = hist[lane * 8 + i]; s += c[i]; }
            unsigned int xs = s;
            #pragma unroll
            for (int o = 1; o < 32; o <<= 1) {
                unsigned int y = __shfl_up_sync(0xffffffffu, xs, o);
                if (lane >= o) xs += y;
            }
            unsigned int tt = __shfl_sync(0xffffffffu, xs, 31);
            unsigned int run = xs - s;
            #pragma unroll
            for (int i = 0; i < 8; i++) {
                unsigned int sfx = tt - run, after = sfx - c[i];
                if (sfx >= krem && after < krem) {
                    sh_sel = (unsigned int)(lane * 8 + i);
                    sh_krem = krem - after;
                    sh_done = (sfx == krem);
                }
                run += c[i];
            }
        }
        __syncthreads();
        pref |= (sh_sel << shift); maskH |= (0xFFu << shift);
        krem = sh_krem; done = sh_done;
        if (done) break;
    }
    const unsigned int T = pref;
    const unsigned int R = done ? (unsigned int)K_ : krem;

    // contiguous-chunk ownership keeps array (= index) order for the rank scan
    const int ept = (cnt + THREADS - 1) / THREADS;   // usually 1
    const int beg = t * ept;
    int end = beg + ept; if (end > cnt) end = cnt;

    unsigned int gt = 0, eq = 0;
    for (int i = beg; i < end; i++) {
        unsigned int u = ckey[i];
        gt += (u > T);
        eq += (u == T);
    }
    unsigned int tot2;
    unsigned int pr = block_scan_excl(gt | (eq << 16), scanB, &tot2);
    unsigned int gtB = pr & 0xFFFFu;
    unsigned int eqB = pr >> 16;

    unsigned int j = gtB + ((eqB < R) ? eqB : R);
    unsigned int eqRank = eqB;
    const size_t idxBase = (size_t)blockIdx.x * K_;
    float* __restrict__ indRow = ind ? (ind + (size_t)b * K_ * D_) : nullptr;
    const float inv_n = 1.0f / (float)N_;

    for (int i = beg; i < end; i++) {
        unsigned int u = ckey[i];
        bool isEq = (u == T);
        bool sel  = (u > T) || (isEq && (eqRank < R));
        eqRank += isEq ? 1u : 0u;
        if (sel) {
            int e = (int)cidx[i];
            if (idxf) idxf[idxBase + j] = (float)e;
            if (indRow) atomicAdd(indRow + (size_t)j * D_ + e, inv_n);
            j++;
        }
    }
}

extern "C" void kernel_launch(void* const* d_in, const int* in_sizes, int n_in,
                              void* d_out, int out_size) {
    const float* x     = (const float*)d_in[0];
    const float* noise = (const float*)d_in[1];
    if (n_in >= 2 && in_sizes[0] != B_ * D_) {
        x     = (const float*)d_in[1];
        noise = (const float*)d_in[0];
    }

    const long long IND = (long long)B_ * K_ * D_;   // 8388608
    const long long IDX = (long long)B_ * N_ * K_;   // 2048000

    float* ind  = nullptr;
    float* idxf = nullptr;
    if ((long long)out_size >= IND + IDX) {
        ind  = (float*)d_out;
        idxf = (float*)d_out + IND;
    } else if ((long long)out_size == IND) {
        ind = (float*)d_out;
    } else if ((long long)out_size == IDX) {
        idxf = (float*)d_out;
    } else {
        ind = (float*)d_out;
    }

    prep_kernel<<<PREP_BLOCKS, THREADS>>>(x, (float4*)ind, (int)(IND / 4));
    perturbed_topk_kernel<<<B_ * N_, THREADS>>>(x, noise, ind, idxf);
}